// round 16
// baseline (speedup 1.0000x reference)
#include <cuda_runtime.h>
#include <math_constants.h>

#define NB 8
#define NT 64
#define NA 100000
#define NF 84
#define BLK 128
#define APT 4
#define APB (BLK * APT)                 // 512 anchors per block
#define GRIDX ((NA + APB - 1) / APB)    // 196
#define NBLOCKS (GRIDX * NB)            // 1568

// scratch (device globals — zero-initialized at module load; last block re-zeros
// them every call, so every graph replay starts clean)
__device__ unsigned long long g_best[NB * NT];
__device__ unsigned int g_ticket;

// ---- packed f32x2 helpers (two independent IEEE-rn lane ops per issue) ----
typedef unsigned long long u64;

__device__ __forceinline__ u64 pk2(float lo, float hi) {
    u64 r; asm("mov.b64 %0, {%1, %2};" : "=l"(r) : "f"(lo), "f"(hi)); return r;
}
__device__ __forceinline__ void upk2(float& lo, float& hi, u64 v) {
    asm("mov.b64 {%0, %1}, %2;" : "=f"(lo), "=f"(hi) : "l"(v));
}
__device__ __forceinline__ u64 add2(u64 a, u64 b) {
    u64 r; asm("add.rn.f32x2 %0, %1, %2;" : "=l"(r) : "l"(a), "l"(b)); return r;
}
__device__ __forceinline__ u64 mul2(u64 a, u64 b) {
    u64 r; asm("mul.rn.f32x2 %0, %1, %2;" : "=l"(r) : "l"(a), "l"(b)); return r;
}
__device__ __forceinline__ u64 fma2(u64 a, u64 b, u64 c) {
    u64 r; asm("fma.rn.f32x2 %0, %1, %2, %3;" : "=l"(r) : "l"(a), "l"(b), "l"(c)); return r;
}
__device__ __forceinline__ float rcp_approx(float d) {
    float r; asm("rcp.approx.f32 %0, %1;" : "=f"(r) : "f"(d)); return r;
}

__global__ void __launch_bounds__(BLK, 12) fused_kernel(
    const float* __restrict__ labels,
    const float* __restrict__ anchors,
    float* __restrict__ out_fore,
    float* __restrict__ out_back,
    float* __restrict__ out_at)
{
    __shared__ float4 sbox[NT];          // x1,y1,x2,y2
    __shared__ u64    sba2[NT];          // (area, area) pre-packed
    __shared__ unsigned long long sbest[NT];
    __shared__ int s_bt[APB];
    __shared__ unsigned int sticket;

    const int b = blockIdx.y;
    const int tid = threadIdx.x;

    if (tid < NT) {
        const float* lb = labels + ((size_t)b * NT + tid) * NF;
        float cx = lb[0], cy = lb[1], w = lb[2], h = lb[3];
        float hw = __fmul_rn(w, 0.5f);
        float hh = __fmul_rn(h, 0.5f);
        float x1 = __fsub_rn(cx, hw);
        float y1 = __fsub_rn(cy, hh);
        float x2 = __fadd_rn(cx, hw);
        float y2 = __fadd_rn(cy, hh);
        sbox[tid] = make_float4(x1, y1, x2, y2);
        float ar = __fmul_rn(__fsub_rn(x2, x1), __fsub_rn(y2, y1));
        sba2[tid] = pk2(ar, ar);
        sbest[tid] = 0ull;
    }
    __syncthreads();

    const int base_a = blockIdx.x * APB;
    const unsigned int sbest_base = (unsigned int)__cvta_generic_to_shared(sbest);

    bool  act[APT];
    float ax1[APT], ay1[APT], ax2[APT], ay2[APT], aareas[APT];
    unsigned int lokey[APT];
    float best_q[APT];
    int   best_t[APT];

#pragma unroll
    for (int j = 0; j < APT; j++) {
        int a = base_a + j * BLK + tid;
        act[j] = (a < NA);
        lokey[j] = 0xFFFFFFFFu - (unsigned int)a;   // smaller idx -> bigger key
        best_q[j] = -1.0f;
        best_t[j] = 0;
        if (act[j]) {
            float4 av = __ldg(((const float4*)anchors) + a);
            float hw = __fmul_rn(av.z, 0.5f);
            float hh = __fmul_rn(av.w, 0.5f);
            ax1[j] = __fsub_rn(av.x, hw);
            ay1[j] = __fsub_rn(av.y, hh);
            ax2[j] = __fadd_rn(av.x, hw);
            ay2[j] = __fadd_rn(av.y, hh);
            aareas[j] = __fmul_rn(__fsub_rn(ax2[j], ax1[j]), __fsub_rn(ay2[j], ay1[j]));
        } else {
            // poison box: forces inter=0 -> q=+0; can never win any argmax
            ax1[j] = CUDART_INF_F;  ay1[j] = CUDART_INF_F;
            ax2[j] = -CUDART_INF_F; ay2[j] = -CUDART_INF_F;
            aareas[j] = 0.0f;
        }
    }

    // prepacked constants / per-anchor-pair areas
    const u64 aarea2[2] = { pk2(aareas[0], aareas[1]), pk2(aareas[2], aareas[3]) };
    const u64 one2  = pk2(1.0f, 1.0f);
    const u64 mone2 = pk2(-1.0f, -1.0f);
    const u64 eps2  = pk2(1e-9f, 1e-9f);

#pragma unroll 4
    for (int t = 0; t < NT; t++) {
        const float4 bb4 = sbox[t];
        const u64    ba2 = sba2[t];
        const unsigned int sb_addr = sbest_base + (unsigned int)t * 8u;

        // scalar min/max network (FMNMX) per anchor
        float ww[APT], hh[APT];
#pragma unroll
        for (int j = 0; j < APT; j++) {
            float ltx = fmaxf(ax1[j], bb4.x);
            float lty = fmaxf(ay1[j], bb4.y);
            float rbx = fminf(ax2[j], bb4.z);
            float rby = fminf(ay2[j], bb4.w);
            ww[j] = fmaxf(__fsub_rn(rbx, ltx), 0.0f);
            hh[j] = fmaxf(__fsub_rn(rby, lty), 0.0f);
        }

        // packed f32x2 IoU tail: inter, denom chain, Markstein divide.
        // Each lane op is the identical IEEE-rn op the scalar version retires
        // => bit-identical results. (-d via mul(d,-1): exact.)
        float q[APT];
#pragma unroll
        for (int p = 0; p < 2; p++) {
            u64 w2 = pk2(ww[2 * p], ww[2 * p + 1]);
            u64 h2 = pk2(hh[2 * p], hh[2 * p + 1]);
            u64 inter2 = mul2(w2, h2);
            // reference: inter / (((area_a + area_b) - inter) + 1e-9)
            u64 s2   = add2(aarea2[p], ba2);
            u64 d2   = add2(fma2(inter2, mone2, s2), eps2);
            float d0, d1; upk2(d0, d1, d2);
            u64 r2   = pk2(rcp_approx(d0), rcp_approx(d1));
            u64 nd2  = mul2(d2, mone2);
            u64 e2   = fma2(nd2, r2, one2);
            r2       = fma2(r2, e2, r2);
            u64 q02  = mul2(inter2, r2);
            u64 rem2 = fma2(nd2, q02, inter2);
            u64 q2   = fma2(rem2, r2, q02);
            upk2(q[2 * p], q[2 * p + 1], q2);
        }

        // per-anchor argmax over t (strict > => first t on ties)
#pragma unroll
        for (int j = 0; j < APT; j++) {
            bool gt = (q[j] > best_q[j]);
            best_q[j] = gt ? q[j] : best_q[j];
            best_t[j] = gt ? t : best_t[j];
        }

        // lexicographic max of (q, lokey) over the 4 anchors (q >= 0 always;
        // strict > on q => lower j (smaller anchor idx / bigger lokey) on ties)
        float qm01 = fmaxf(q[0], q[1]);
        unsigned int l01 = (q[1] > q[0]) ? lokey[1] : lokey[0];
        float qm23 = fmaxf(q[2], q[3]);
        unsigned int l23 = (q[3] > q[2]) ? lokey[3] : lokey[2];
        float qm = fmaxf(qm01, qm23);
        unsigned int lsel = (qm23 > qm01) ? l23 : l01;
        unsigned int qmbits = __float_as_uint(qm);
        unsigned long long key =
            ((unsigned long long)qmbits << 32) | (unsigned long long)lsel;

        // warp-level pre-reduction + unconditional election: exactly the
        // warp-max lane(s) fire the red (ties at nonzero q are measure-zero,
        // so ~1 lane/warp/t). No stale-read filter => no per-t asm LDS fence.
        unsigned int wmax = __reduce_max_sync(0xFFFFFFFFu, qmbits);
        asm volatile(
            "{\n\t"
            ".reg .pred p;\n\t"
            "setp.eq.u32 p, %1, %2;\n\t"
            "@p red.shared.max.u64 [%0], %3;\n\t"
            "}"
            :: "r"(sb_addr), "r"(qmbits), "r"(wmax), "l"(key)
            : "memory");
    }

#pragma unroll
    for (int j = 0; j < APT; j++) {
        s_bt[j * BLK + tid] = best_t[j];
        if (act[j]) {
            bool fore = (best_q[j] >= 0.5f);
            bool back = (!fore) && (best_q[j] < 0.4f);
            size_t o = (size_t)b * NA + (base_a + j * BLK + tid);
            out_fore[o] = fore ? 1.0f : 0.0f;
            out_back[o] = back ? 1.0f : 0.0f;
        }
    }

    __syncthreads();
    if (tid < NT) atomicMax(&g_best[b * NT + tid], sbest[tid]);

    // fused gather: assigned_target[b, a, :] = labels[b, best_t[a], :]
    // (84 f32 = 21 float4 per anchor; labels rows are 336B = 16B-aligned)
    const float4* lbase = (const float4*)(labels + (size_t)b * NT * NF);
    float* obase = out_at + ((size_t)b * NA + base_a) * NF;
    {
        int al = tid / 21;
        int qq = tid - al * 21;
#pragma unroll 4
        for (int idx = tid; idx < APB * 21; idx += BLK) {
            if (base_a + al < NA) {
                int t = s_bt[al];
                float4 v = __ldg(lbase + t * 21 + qq);
                __stcs((float4*)(obase + (size_t)al * NF) + qq, v);
            }
            al += 6; qq += 2;             // BLK=128 = 6*21 + 2
            if (qq >= 21) { qq -= 21; al += 1; }
        }
    }

    // ---- last-block MAX_FOR_TARGET fixup (replaces init + winner kernels) ----
    __threadfence();
    if (tid == 0) sticket = atomicAdd(&g_ticket, 1u);
    __syncthreads();
    if (sticket == NBLOCKS - 1) {
        __threadfence();
        for (int i = tid; i < NB * NT; i += BLK) {
            unsigned long long key = *((volatile unsigned long long*)&g_best[i]);
            int bb = i >> 6;  // / NT
            unsigned int a = 0xFFFFFFFFu - (unsigned int)(key & 0xFFFFFFFFull);
            size_t o = (size_t)bb * NA + a;
            out_fore[o] = 1.0f;   // winning anchor per (b,t): always foreground
            out_back[o] = 0.0f;
            g_best[i] = 0ull;     // reset for next graph replay
        }
        __threadfence();
        if (tid == 0) g_ticket = 0u;
    }
}

extern "C" void kernel_launch(void* const* d_in, const int* in_sizes, int n_in,
                              void* d_out, int out_size)
{
    const float* labels;
    const float* anchors;
    // labels = 8*64*84 = 43008 elems, anchors = 1*100000*4 = 400000 elems
    if (in_sizes[0] == NB * NT * NF) {
        labels  = (const float*)d_in[0];
        anchors = (const float*)d_in[1];
    } else {
        labels  = (const float*)d_in[1];
        anchors = (const float*)d_in[0];
    }

    float* out      = (float*)d_out;
    float* out_fore = out;
    float* out_back = out + (size_t)NB * NA;
    float* out_at   = out + (size_t)2 * NB * NA;

    dim3 grid(GRIDX, NB);
    fused_kernel<<<grid, BLK>>>(labels, anchors, out_fore, out_back, out_at);
}

// round 17
// speedup vs baseline: 1.0721x; 1.0721x over previous
#include <cuda_runtime.h>
#include <math_constants.h>

#define NB 8
#define NT 64
#define NA 100000
#define NF 84
#define BLK 128
#define APT 4
#define APB (BLK * APT)                 // 512 anchors per block
#define GRIDX ((NA + APB - 1) / APB)    // 196
#define NBLOCKS (GRIDX * NB)            // 1568

// scratch (device globals — zero-initialized at module load; last block re-zeros
// them every call, so every graph replay starts clean)
__device__ unsigned long long g_best[NB * NT];
__device__ unsigned int g_ticket;

// ---- packed f32x2 helpers (two independent IEEE-rn lane ops per issue) ----
typedef unsigned long long u64;

__device__ __forceinline__ u64 pk2(float lo, float hi) {
    u64 r; asm("mov.b64 %0, {%1, %2};" : "=l"(r) : "f"(lo), "f"(hi)); return r;
}
__device__ __forceinline__ void upk2(float& lo, float& hi, u64 v) {
    asm("mov.b64 {%0, %1}, %2;" : "=f"(lo), "=f"(hi) : "l"(v));
}
__device__ __forceinline__ u64 add2(u64 a, u64 b) {
    u64 r; asm("add.rn.f32x2 %0, %1, %2;" : "=l"(r) : "l"(a), "l"(b)); return r;
}
__device__ __forceinline__ u64 mul2(u64 a, u64 b) {
    u64 r; asm("mul.rn.f32x2 %0, %1, %2;" : "=l"(r) : "l"(a), "l"(b)); return r;
}
__device__ __forceinline__ u64 fma2(u64 a, u64 b, u64 c) {
    u64 r; asm("fma.rn.f32x2 %0, %1, %2, %3;" : "=l"(r) : "l"(a), "l"(b), "l"(c)); return r;
}
__device__ __forceinline__ float rcp_approx(float d) {
    float r; asm("rcp.approx.f32 %0, %1;" : "=f"(r) : "f"(d)); return r;
}

__global__ void __launch_bounds__(BLK) fused_kernel(
    const float* __restrict__ labels,
    const float* __restrict__ anchors,
    float* __restrict__ out_fore,
    float* __restrict__ out_back,
    float* __restrict__ out_at)
{
    __shared__ float4 sbox[NT];          // x1,y1,x2,y2
    __shared__ u64    sba2[NT];          // (area, area) pre-packed
    __shared__ unsigned long long sbest[NT];
    __shared__ int s_bt[APB];
    __shared__ unsigned int sticket;

    const int b = blockIdx.y;
    const int tid = threadIdx.x;

    if (tid < NT) {
        const float* lb = labels + ((size_t)b * NT + tid) * NF;
        float cx = lb[0], cy = lb[1], w = lb[2], h = lb[3];
        float hw = __fmul_rn(w, 0.5f);
        float hh = __fmul_rn(h, 0.5f);
        float x1 = __fsub_rn(cx, hw);
        float y1 = __fsub_rn(cy, hh);
        float x2 = __fadd_rn(cx, hw);
        float y2 = __fadd_rn(cy, hh);
        sbox[tid] = make_float4(x1, y1, x2, y2);
        float ar = __fmul_rn(__fsub_rn(x2, x1), __fsub_rn(y2, y1));
        sba2[tid] = pk2(ar, ar);
        sbest[tid] = 0ull;
    }
    __syncthreads();

    const int base_a = blockIdx.x * APB;
    const unsigned int sbest_base = (unsigned int)__cvta_generic_to_shared(sbest);

    bool  act[APT];
    float ax1[APT], ay1[APT], ax2[APT], ay2[APT], aareas[APT];
    unsigned int lokey[APT];
    float best_q[APT];
    int   best_t[APT];

#pragma unroll
    for (int j = 0; j < APT; j++) {
        int a = base_a + j * BLK + tid;
        act[j] = (a < NA);
        lokey[j] = 0xFFFFFFFFu - (unsigned int)a;   // smaller idx -> bigger key
        best_q[j] = -1.0f;
        best_t[j] = 0;
        if (act[j]) {
            float4 av = __ldg(((const float4*)anchors) + a);
            float hw = __fmul_rn(av.z, 0.5f);
            float hh = __fmul_rn(av.w, 0.5f);
            ax1[j] = __fsub_rn(av.x, hw);
            ay1[j] = __fsub_rn(av.y, hh);
            ax2[j] = __fadd_rn(av.x, hw);
            ay2[j] = __fadd_rn(av.y, hh);
            aareas[j] = __fmul_rn(__fsub_rn(ax2[j], ax1[j]), __fsub_rn(ay2[j], ay1[j]));
        } else {
            // poison box: forces inter=0 -> q=+0; can never win any argmax
            ax1[j] = CUDART_INF_F;  ay1[j] = CUDART_INF_F;
            ax2[j] = -CUDART_INF_F; ay2[j] = -CUDART_INF_F;
            aareas[j] = 0.0f;
        }
    }

    // prepacked constants / per-anchor-pair areas
    const u64 aarea2[2] = { pk2(aareas[0], aareas[1]), pk2(aareas[2], aareas[3]) };
    const u64 one2  = pk2(1.0f, 1.0f);
    const u64 mone2 = pk2(-1.0f, -1.0f);
    const u64 eps2  = pk2(1e-9f, 1e-9f);

#pragma unroll 8
    for (int t = 0; t < NT; t++) {
        const float4 bb4 = sbox[t];
        const u64    ba2 = sba2[t];
        const unsigned int sb_addr = sbest_base + (unsigned int)t * 8u;

        // scalar min/max network (FMNMX) per anchor
        float ww[APT], hh[APT];
#pragma unroll
        for (int j = 0; j < APT; j++) {
            float ltx = fmaxf(ax1[j], bb4.x);
            float lty = fmaxf(ay1[j], bb4.y);
            float rbx = fminf(ax2[j], bb4.z);
            float rby = fminf(ay2[j], bb4.w);
            ww[j] = fmaxf(__fsub_rn(rbx, ltx), 0.0f);
            hh[j] = fmaxf(__fsub_rn(rby, lty), 0.0f);
        }

        // packed f32x2 IoU tail: inter, denom chain, Markstein divide.
        // Each lane op is the identical IEEE-rn op the scalar version retires
        // => bit-identical results. (-d via mul(d,-1): exact.)
        float q[APT];
#pragma unroll
        for (int p = 0; p < 2; p++) {
            u64 w2 = pk2(ww[2 * p], ww[2 * p + 1]);
            u64 h2 = pk2(hh[2 * p], hh[2 * p + 1]);
            u64 inter2 = mul2(w2, h2);
            // reference: inter / (((area_a + area_b) - inter) + 1e-9)
            u64 s2   = add2(aarea2[p], ba2);
            u64 d2   = add2(fma2(inter2, mone2, s2), eps2);
            float d0, d1; upk2(d0, d1, d2);
            u64 r2   = pk2(rcp_approx(d0), rcp_approx(d1));
            u64 nd2  = mul2(d2, mone2);
            u64 e2   = fma2(nd2, r2, one2);
            r2       = fma2(r2, e2, r2);
            u64 q02  = mul2(inter2, r2);
            u64 rem2 = fma2(nd2, q02, inter2);
            u64 q2   = fma2(rem2, r2, q02);
            upk2(q[2 * p], q[2 * p + 1], q2);
        }

        // per-anchor argmax over t (strict > => first t on ties)
#pragma unroll
        for (int j = 0; j < APT; j++) {
            bool gt = (q[j] > best_q[j]);
            best_q[j] = gt ? q[j] : best_q[j];
            best_t[j] = gt ? t : best_t[j];
        }

        // lexicographic max of (q, lokey) over the 4 anchors (q >= 0 always;
        // strict > on q => lower j (smaller anchor idx / bigger lokey) on ties)
        float qm01 = fmaxf(q[0], q[1]);
        unsigned int l01 = (q[1] > q[0]) ? lokey[1] : lokey[0];
        float qm23 = fmaxf(q[2], q[3]);
        unsigned int l23 = (q[3] > q[2]) ? lokey[3] : lokey[2];
        float qm = fmaxf(qm01, qm23);
        unsigned int lsel = (qm23 > qm01) ? l23 : l01;
        unsigned int qmbits = __float_as_uint(qm);
        unsigned long long key =
            ((unsigned long long)qmbits << 32) | (unsigned long long)lsel;

        // warp-level pre-reduction + unconditional election: exactly the
        // warp-max lane(s) fire the red (ties at nonzero q are measure-zero,
        // so ~1 lane/warp/t). No stale-read filter => no per-t asm LDS fence.
        unsigned int wmax = __reduce_max_sync(0xFFFFFFFFu, qmbits);
        asm volatile(
            "{\n\t"
            ".reg .pred p;\n\t"
            "setp.eq.u32 p, %1, %2;\n\t"
            "@p red.shared.max.u64 [%0], %3;\n\t"
            "}"
            :: "r"(sb_addr), "r"(qmbits), "r"(wmax), "l"(key)
            : "memory");
    }

#pragma unroll
    for (int j = 0; j < APT; j++) {
        s_bt[j * BLK + tid] = best_t[j];
        if (act[j]) {
            bool fore = (best_q[j] >= 0.5f);
            bool back = (!fore) && (best_q[j] < 0.4f);
            size_t o = (size_t)b * NA + (base_a + j * BLK + tid);
            out_fore[o] = fore ? 1.0f : 0.0f;
            out_back[o] = back ? 1.0f : 0.0f;
        }
    }

    __syncthreads();
    if (tid < NT) atomicMax(&g_best[b * NT + tid], sbest[tid]);

    // fused gather: assigned_target[b, a, :] = labels[b, best_t[a], :]
    // (84 f32 = 21 float4 per anchor; labels rows are 336B = 16B-aligned)
    const float4* lbase = (const float4*)(labels + (size_t)b * NT * NF);
    float* obase = out_at + ((size_t)b * NA + base_a) * NF;
    {
        int al = tid / 21;
        int qq = tid - al * 21;
#pragma unroll 4
        for (int idx = tid; idx < APB * 21; idx += BLK) {
            if (base_a + al < NA) {
                int t = s_bt[al];
                float4 v = __ldg(lbase + t * 21 + qq);
                __stcs((float4*)(obase + (size_t)al * NF) + qq, v);
            }
            al += 6; qq += 2;             // BLK=128 = 6*21 + 2
            if (qq >= 21) { qq -= 21; al += 1; }
        }
    }

    // ---- last-block MAX_FOR_TARGET fixup (replaces init + winner kernels) ----
    __threadfence();
    if (tid == 0) sticket = atomicAdd(&g_ticket, 1u);
    __syncthreads();
    if (sticket == NBLOCKS - 1) {
        __threadfence();
        for (int i = tid; i < NB * NT; i += BLK) {
            unsigned long long key = *((volatile unsigned long long*)&g_best[i]);
            int bb = i >> 6;  // / NT
            unsigned int a = 0xFFFFFFFFu - (unsigned int)(key & 0xFFFFFFFFull);
            size_t o = (size_t)bb * NA + a;
            out_fore[o] = 1.0f;   // winning anchor per (b,t): always foreground
            out_back[o] = 0.0f;
            g_best[i] = 0ull;     // reset for next graph replay
        }
        __threadfence();
        if (tid == 0) g_ticket = 0u;
    }
}

extern "C" void kernel_launch(void* const* d_in, const int* in_sizes, int n_in,
                              void* d_out, int out_size)
{
    const float* labels;
    const float* anchors;
    // labels = 8*64*84 = 43008 elems, anchors = 1*100000*4 = 400000 elems
    if (in_sizes[0] == NB * NT * NF) {
        labels  = (const float*)d_in[0];
        anchors = (const float*)d_in[1];
    } else {
        labels  = (const float*)d_in[1];
        anchors = (const float*)d_in[0];
    }

    float* out      = (float*)d_out;
    float* out_fore = out;
    float* out_back = out + (size_t)NB * NA;
    float* out_at   = out + (size_t)2 * NB * NA;

    dim3 grid(GRIDX, NB);
    fused_kernel<<<grid, BLK>>>(labels, anchors, out_fore, out_back, out_at);
}